// round 1
// baseline (speedup 1.0000x reference)
#include <cuda_runtime.h>
#include <cuda_bf16.h>

// PLIF neuron scan over T=8 timesteps.
// x: [B=32, T=8, C=128, H=32, W=32] fp32, w: scalar fp32.
// out: spikes, same shape as x.
//
// Strategy: one thread per 4 contiguous spatial lanes (float4). All 8
// timestep loads are independent of the recurrence -> front-batch them
// (MLP=8), then run the sequential membrane scan in registers, then store.

#define VTH 0.5f

__global__ __launch_bounds__(256) void plif_kernel(
    const float4* __restrict__ x,
    const float* __restrict__ w,
    float4* __restrict__ out,
    int total4,   // B * S4 total float4 sites
    int S4)       // spatial float4 count per (b,t) = C*H*W/4
{
    int i = blockIdx.x * blockDim.x + threadIdx.x;
    if (i >= total4) return;

    int b = i / S4;
    int s = i - b * S4;

    // tau = sigmoid(w). Scalar broadcast load, L1-cached; MUFU cost negligible.
    float wv = *w;
    float tau = 1.0f / (1.0f + __expf(-wv));

    // Base offset of (b, t=0) in float4 units; timestep stride is S4*T? No:
    // flat layout [B,T,S] -> offset(b,t) = (b*8 + t) * S4.
    long base = ((long)b * 8) * S4 + s;

    // Front-batch all 8 loads (independent of the recurrence) for MLP=8.
    float4 xv[8];
#pragma unroll
    for (int t = 0; t < 8; t++) {
        xv[t] = x[base + (long)t * S4];
    }

    // Sequential scan per lane.
    float4 m = make_float4(0.f, 0.f, 0.f, 0.f);
    float4 sp[8];
#pragma unroll
    for (int t = 0; t < 8; t++) {
        float4 r;
        // lane x
        m.x = fmaf(tau, m.x, xv[t].x);
        r.x = (m.x > VTH) ? 1.0f : 0.0f;
        m.x = (m.x > VTH) ? 0.0f : m.x;
        // lane y
        m.y = fmaf(tau, m.y, xv[t].y);
        r.y = (m.y > VTH) ? 1.0f : 0.0f;
        m.y = (m.y > VTH) ? 0.0f : m.y;
        // lane z
        m.z = fmaf(tau, m.z, xv[t].z);
        r.z = (m.z > VTH) ? 1.0f : 0.0f;
        m.z = (m.z > VTH) ? 0.0f : m.z;
        // lane w
        m.w = fmaf(tau, m.w, xv[t].w);
        r.w = (m.w > VTH) ? 1.0f : 0.0f;
        m.w = (m.w > VTH) ? 0.0f : m.w;
        sp[t] = r;
    }

#pragma unroll
    for (int t = 0; t < 8; t++) {
        out[base + (long)t * S4] = sp[t];
    }
}

extern "C" void kernel_launch(void* const* d_in, const int* in_sizes, int n_in,
                              void* d_out, int out_size) {
    const float* x = (const float*)d_in[0];
    const float* w = (const float*)d_in[1];
    float* o = (float*)d_out;

    // x: [32, 8, 128, 32, 32] -> B=32, T=8, S = 128*32*32 = 131072
    const int B = 32;
    const int S = 131072;
    const int S4 = S / 4;          // 32768
    const int total4 = B * S4;     // 1,048,576

    int threads = 256;
    int blocks = (total4 + threads - 1) / threads;
    plif_kernel<<<blocks, threads>>>((const float4*)x, w, (float4*)o, total4, S4);
}

// round 3
// speedup vs baseline: 1.0455x; 1.0455x over previous
#include <cuda_runtime.h>
#include <cuda_bf16.h>

// PLIF neuron scan, T=8.
// x: [B=32, T=8, C=128, H=32, W=32] fp32 -> [B=32, T=8, S=131072].
// Pure streaming: 128MB read + 128MB write, no reuse -> HBM-bound.
//
// One thread = 4 contiguous spatial lanes (float4) x 8 timesteps.
// All 8 loads are independent of the recurrence -> issued up front (MLP=8).
// Spikes are stored immediately per timestep (no output buffering) so the
// full 8x float4 load batch stays live without spills. Streaming hints
// (__ldcs/__stcs) since no byte is ever touched twice.

#define VTH 0.5f
#define S4C 32768u      // spatial float4 per (b,t) = 128*32*32/4
#define S4_SHIFT 15
#define S4_MASK 32767

__global__ __launch_bounds__(256) void plif_kernel(
    const float4* __restrict__ x,
    const float* __restrict__ w,
    float4* __restrict__ out)
{
    unsigned i = blockIdx.x * blockDim.x + threadIdx.x;  // 0..1048575 exact
    unsigned b = i >> S4_SHIFT;
    unsigned s = i & S4_MASK;

    float wv = __ldg(w);
    float tau = 1.0f / (1.0f + __expf(-wv));

    unsigned base = (b << 3) * S4C + s;   // (b, t=0, s); max 8M < 2^32 float4s
    const float4* px = x + base;
    float4* po = out + base;

    // Front-batch all 8 timestep loads: independent of the scan -> MLP=8.
    float4 xv[8];
#pragma unroll
    for (int t = 0; t < 8; t++) {
        xv[t] = __ldcs(px + t * S4C);
    }

    // Sequential membrane scan; store each spike vector immediately.
    float4 m = make_float4(0.f, 0.f, 0.f, 0.f);
#pragma unroll
    for (int t = 0; t < 8; t++) {
        float4 r;

        m.x = fmaf(tau, m.x, xv[t].x);
        r.x = (m.x > VTH) ? 1.0f : 0.0f;
        m.x = (m.x > VTH) ? 0.0f : m.x;

        m.y = fmaf(tau, m.y, xv[t].y);
        r.y = (m.y > VTH) ? 1.0f : 0.0f;
        m.y = (m.y > VTH) ? 0.0f : m.y;

        m.z = fmaf(tau, m.z, xv[t].z);
        r.z = (m.z > VTH) ? 1.0f : 0.0f;
        m.z = (m.z > VTH) ? 0.0f : m.z;

        m.w = fmaf(tau, m.w, xv[t].w);
        r.w = (m.w > VTH) ? 1.0f : 0.0f;
        m.w = (m.w > VTH) ? 0.0f : m.w;

        __stcs(po + t * S4C, r);
    }
}

extern "C" void kernel_launch(void* const* d_in, const int* in_sizes, int n_in,
                              void* d_out, int out_size) {
    const float4* x = (const float4*)d_in[0];
    const float* w = (const float*)d_in[1];
    float4* o = (float4*)d_out;

    // total float4 sites = 32 * 32768 = 1,048,576 -> exact 4096 x 256 grid
    plif_kernel<<<4096, 256>>>(x, w, o);
}